// round 4
// baseline (speedup 1.0000x reference)
#include <cuda_runtime.h>

#define MAX_CHUNKS 8
// Partial T: [chunk][o][i], alpha folded in. 8*1024 floats max.
__device__ float g_Tp[MAX_CHUNKS * 8192];
// Full T for generic fallback path.
__device__ float g_T[8192];

// Sign of e_a * e_b reordering for Cl(3,0) (all metric signs +1).
__device__ __forceinline__ float blade_sign(int a, int b) {
    int swaps = 0;
    int t = a >> 1;
    while (t) { swaps += __popc(t & b); t >>= 1; }
    return (swaps & 1) ? -1.0f : 1.0f;
}

// Shared inner body: acc[i] += sum_j c[i][j]*win[j]*wout[i^j]
#define CLIFFORD_CIJ()                                             \
    float sigma[8];                                                \
    _Pragma("unroll")                                              \
    for (int k = 0; k < 8; k++) sigma[k] = blade_sign(k, k);       \
    float cij[8][8];                                               \
    _Pragma("unroll")                                              \
    for (int i = 0; i < 8; i++)                                    \
        _Pragma("unroll")                                          \
        for (int j = 0; j < 8; j++)                                \
            cij[i][j] = blade_sign(i, j) * sigma[i ^ j];

// Partial T over an H-chunk: grid (O, NCHUNK), 128 threads.
__global__ __launch_bounds__(128)
void compute_T_partial(const float* __restrict__ W_in,
                       const float* __restrict__ W_out,
                       int H, int Hc, float alpha)
{
    const int o = blockIdx.x;
    const int c = blockIdx.y;
    const int O = gridDim.x;
    const int tid = threadIdx.x;

    CLIFFORD_CIJ();

    float acc[8];
    #pragma unroll
    for (int i = 0; i < 8; i++) acc[i] = 0.0f;

    const int h0 = c * Hc;
    const float* woutBase = W_out + ((size_t)o * H + h0) * 8;
    const float* winBase  = W_in + (size_t)h0 * 8;
    for (int h = tid; h < Hc; h += blockDim.x) {
        float4 a0 = *(const float4*)(winBase + h * 8);
        float4 a1 = *(const float4*)(winBase + h * 8 + 4);
        float4 b0 = *(const float4*)(woutBase + h * 8);
        float4 b1 = *(const float4*)(woutBase + h * 8 + 4);
        float win[8]  = {a0.x, a0.y, a0.z, a0.w, a1.x, a1.y, a1.z, a1.w};
        float wout[8] = {b0.x, b0.y, b0.z, b0.w, b1.x, b1.y, b1.z, b1.w};
        #pragma unroll
        for (int i = 0; i < 8; i++) {
            float s = 0.0f;
            #pragma unroll
            for (int j = 0; j < 8; j++)
                s += cij[i][j] * win[j] * wout[i ^ j];
            acc[i] += s;
        }
    }

    #pragma unroll
    for (int i = 0; i < 8; i++) {
        #pragma unroll
        for (int off = 16; off > 0; off >>= 1)
            acc[i] += __shfl_xor_sync(0xffffffff, acc[i], off);
    }

    __shared__ float red[4][8];
    const int lane = tid & 31, w = tid >> 5;
    if (lane == 0) {
        #pragma unroll
        for (int i = 0; i < 8; i++) red[w][i] = acc[i];
    }
    __syncthreads();
    if (tid < 8) {
        float s = red[0][tid] + red[1][tid] + red[2][tid] + red[3][tid];
        g_Tp[(c * O + o) * 8 + tid] = alpha * s;
    }
}

// Flat finalize (O==128): 8 batch rows per block, thread = (row, o-group).
#define FB_ROWS 8
__global__ __launch_bounds__(256)
void finalize128_flat(const float* __restrict__ x,
                      float* __restrict__ out, int nchunks)
{
    __shared__ float Ts[32 * 33];     // 32 o-groups x 32 floats, stride 33
    __shared__ float xs[FB_ROWS * 9];

    const int tid = threadIdx.x;
    for (int idx = tid; idx < 1024; idx += 256) {
        float s = 0.0f;
        #pragma unroll 4
        for (int cc = 0; cc < nchunks; cc++) s += g_Tp[cc * 1024 + idx];
        Ts[(idx >> 5) * 33 + (idx & 31)] = s;
    }
    const int b0 = blockIdx.x * FB_ROWS;
    if (tid < FB_ROWS * 8)
        xs[(tid >> 3) * 9 + (tid & 7)] = x[b0 * 8 + tid];
    __syncthreads();

    const int og = tid & 31;
    const int bl = tid >> 5;   // 0..7

    float t[32];
    #pragma unroll
    for (int k = 0; k < 32; k++) t[k] = Ts[og * 33 + k];   // conflict-free
    float xv[8];
    #pragma unroll
    for (int i = 0; i < 8; i++) xv[i] = xs[bl * 9 + i];    // warp broadcast

    float s0 = 0, s1 = 0, s2 = 0, s3 = 0;
    #pragma unroll
    for (int i = 0; i < 8; i++) {
        s0 += xv[i] * t[i];
        s1 += xv[i] * t[8 + i];
        s2 += xv[i] * t[16 + i];
        s3 += xv[i] * t[24 + i];
    }
    float4 o4 = {s0, s1, s2, s3};
    *(float4*)(out + (size_t)(b0 + bl) * 128 + og * 4) = o4;
}

// ---------- generic fallback path (any O/H/B) ----------
__global__ void compute_T_kernel(const float* __restrict__ W_in,
                                 const float* __restrict__ W_out,
                                 int H, float alpha)
{
    const int o = blockIdx.x;
    const int tid = threadIdx.x;
    CLIFFORD_CIJ();
    float acc[8];
    #pragma unroll
    for (int i = 0; i < 8; i++) acc[i] = 0.0f;
    const float* woutBase = W_out + (size_t)o * H * 8;
    for (int h = tid; h < H; h += blockDim.x) {
        float4 a0 = *(const float4*)(W_in + h * 8);
        float4 a1 = *(const float4*)(W_in + h * 8 + 4);
        float4 b0 = *(const float4*)(woutBase + h * 8);
        float4 b1 = *(const float4*)(woutBase + h * 8 + 4);
        float win[8]  = {a0.x, a0.y, a0.z, a0.w, a1.x, a1.y, a1.z, a1.w};
        float wout[8] = {b0.x, b0.y, b0.z, b0.w, b1.x, b1.y, b1.z, b1.w};
        #pragma unroll
        for (int i = 0; i < 8; i++) {
            float s = 0.0f;
            #pragma unroll
            for (int j = 0; j < 8; j++)
                s += cij[i][j] * win[j] * wout[i ^ j];
            acc[i] += s;
        }
    }
    #pragma unroll
    for (int i = 0; i < 8; i++)
        #pragma unroll
        for (int off = 16; off > 0; off >>= 1)
            acc[i] += __shfl_xor_sync(0xffffffff, acc[i], off);
    __shared__ float red[8][8];
    const int lane = tid & 31, w = tid >> 5;
    const int nw = blockDim.x >> 5;
    if (lane == 0) {
        #pragma unroll
        for (int i = 0; i < 8; i++) red[w][i] = acc[i];
    }
    __syncthreads();
    if (tid < 8) {
        float s = 0.0f;
        for (int ww = 0; ww < nw; ww++) s += red[ww][tid];
        g_T[o * 8 + tid] = alpha * s;
    }
}

__global__ void finalize_generic_kernel(const float* __restrict__ x,
                                        float* __restrict__ out, int O)
{
    extern __shared__ float Tg[];  // [8][O] transposed
    for (int idx = threadIdx.x; idx < O * 8; idx += blockDim.x) {
        int o = idx >> 3, i = idx & 7;
        Tg[i * O + o] = g_T[idx];
    }
    __syncthreads();
    const int b = blockIdx.x;
    float4 x0 = *(const float4*)(x + b * 8);
    float4 x1 = *(const float4*)(x + b * 8 + 4);
    for (int o = threadIdx.x; o < O; o += blockDim.x) {
        float s = x0.x * Tg[o]         + x0.y * Tg[O + o]
                + x0.z * Tg[2 * O + o] + x0.w * Tg[3 * O + o]
                + x1.x * Tg[4 * O + o] + x1.y * Tg[5 * O + o]
                + x1.z * Tg[6 * O + o] + x1.w * Tg[7 * O + o];
        out[(size_t)b * O + o] = s;
    }
}

extern "C" void kernel_launch(void* const* d_in, const int* in_sizes, int n_in,
                              void* d_out, int out_size)
{
    const float* x     = (const float*)d_in[0];  // [B,8]
    const float* W_in  = (const float*)d_in[1];  // [H,1,8]
    const float* W_out = (const float*)d_in[2];  // [O,H,8]

    const int B = in_sizes[0] / 8;
    const int H = in_sizes[1] / 8;
    const int O = in_sizes[2] / (H * 8);

    // alpha = 1 - (1-dt)^n_free, dt=0.1, n_free=10
    double p = 1.0;
    for (int i = 0; i < 10; i++) p *= 0.9;
    const float alpha = (float)(1.0 - p);

    const int nchunks = 4;
    if (O == 128 && (B % FB_ROWS) == 0 && (H % nchunks) == 0) {
        dim3 gT(O, nchunks);
        compute_T_partial<<<gT, 128>>>(W_in, W_out, H, H / nchunks, alpha);
        finalize128_flat<<<B / FB_ROWS, 256>>>(x, (float*)d_out, nchunks);
    } else {
        compute_T_kernel<<<O, 256>>>(W_in, W_out, H, alpha);
        finalize_generic_kernel<<<B, 128, O * 8 * sizeof(float)>>>(x, (float*)d_out, O);
    }
}

// round 5
// speedup vs baseline: 1.0619x; 1.0619x over previous
#include <cuda_runtime.h>

// Precontracted weight matrix T[o][i], alpha folded in.
__device__ float g_T[8192];
// Producer->consumer handshake counter (memset to 0 before each launch).
__device__ unsigned g_done;

// Sign of e_a * e_b reordering for Cl(3,0) (all metric signs +1).
__device__ __forceinline__ float blade_sign(int a, int b) {
    int swaps = 0;
    int t = a >> 1;
    while (t) { swaps += __popc(t & b); t >>= 1; }
    return (swaps & 1) ? -1.0f : 1.0f;
}

#define CLIFFORD_CIJ()                                             \
    float sigma[8];                                                \
    _Pragma("unroll")                                              \
    for (int k = 0; k < 8; k++) sigma[k] = blade_sign(k, k);       \
    float cij[8][8];                                               \
    _Pragma("unroll")                                              \
    for (int i = 0; i < 8; i++)                                    \
        _Pragma("unroll")                                          \
        for (int j = 0; j < 8; j++)                                \
            cij[i][j] = blade_sign(i, j) * sigma[i ^ j];

// Fused kernel: blocks [0, O) produce T; blocks [O, O + B/16) consume.
// All blocks are co-resident (grid <= 384 blocks of 256 threads), so the
// spin-wait is deadlock-free.
#define F_ROWS 16
__global__ __launch_bounds__(256)
void fused_kernel(const float* __restrict__ x,
                  const float* __restrict__ W_in,
                  const float* __restrict__ W_out,
                  float* __restrict__ out,
                  int H, int O, float alpha)
{
    const int tid = threadIdx.x;
    const int bid = blockIdx.x;

    if (bid < O) {
        // ---------------- producer: T[o,i] ----------------
        const int o = bid;
        CLIFFORD_CIJ();
        float acc[8];
        #pragma unroll
        for (int i = 0; i < 8; i++) acc[i] = 0.0f;

        const float* woutBase = W_out + (size_t)o * H * 8;
        for (int h = tid; h < H; h += 256) {
            float4 a0 = *(const float4*)(W_in + h * 8);
            float4 a1 = *(const float4*)(W_in + h * 8 + 4);
            float4 b0 = *(const float4*)(woutBase + h * 8);
            float4 b1 = *(const float4*)(woutBase + h * 8 + 4);
            float win[8]  = {a0.x, a0.y, a0.z, a0.w, a1.x, a1.y, a1.z, a1.w};
            float wout[8] = {b0.x, b0.y, b0.z, b0.w, b1.x, b1.y, b1.z, b1.w};
            #pragma unroll
            for (int i = 0; i < 8; i++) {
                float s = 0.0f;
                #pragma unroll
                for (int j = 0; j < 8; j++)
                    s += cij[i][j] * win[j] * wout[i ^ j];
                acc[i] += s;
            }
        }
        #pragma unroll
        for (int i = 0; i < 8; i++)
            #pragma unroll
            for (int off = 16; off > 0; off >>= 1)
                acc[i] += __shfl_xor_sync(0xffffffff, acc[i], off);

        __shared__ float red[8][8];
        const int lane = tid & 31, w = tid >> 5;
        if (lane == 0) {
            #pragma unroll
            for (int i = 0; i < 8; i++) red[w][i] = acc[i];
        }
        __syncthreads();
        if (tid < 8) {
            float s = 0.0f;
            #pragma unroll
            for (int ww = 0; ww < 8; ww++) s += red[ww][tid];
            g_T[o * 8 + tid] = alpha * s;
        }
        // release: make g_T stores device-visible, then bump counter
        __threadfence();
        __syncthreads();
        if (tid == 0) atomicAdd(&g_done, 1u);
    } else {
        // ---------------- consumer: out rows ----------------
        __shared__ float Ts[32 * 33];    // 32 o-groups x 32 floats, stride 33
        __shared__ float xs[F_ROWS * 9];

        const int b0 = (bid - O) * F_ROWS;
        // stage x while producers run
        if (tid < F_ROWS * 8)
            xs[(tid >> 3) * 9 + (tid & 7)] = x[b0 * 8 + tid];

        // wait for all O producers
        if (tid == 0) {
            while (*(volatile unsigned*)&g_done < (unsigned)O)
                __nanosleep(64);
        }
        __syncthreads();
        __threadfence();   // acquire: order g_T reads after the flag

        for (int idx = tid; idx < 1024; idx += 256)
            Ts[(idx >> 5) * 33 + (idx & 31)] = g_T[idx];
        __syncthreads();

        const int og = tid & 31;
        const int bq = tid >> 5;   // 0..7

        float t[32];
        #pragma unroll
        for (int k = 0; k < 32; k++) t[k] = Ts[og * 33 + k];  // conflict-free

        #pragma unroll
        for (int r = 0; r < F_ROWS / 8; r++) {
            const int bl = bq + r * 8;
            float xv[8];
            #pragma unroll
            for (int i = 0; i < 8; i++) xv[i] = xs[bl * 9 + i];

            float s0 = 0, s1 = 0, s2 = 0, s3 = 0;
            #pragma unroll
            for (int i = 0; i < 8; i++) {
                s0 += xv[i] * t[i];
                s1 += xv[i] * t[8 + i];
                s2 += xv[i] * t[16 + i];
                s3 += xv[i] * t[24 + i];
            }
            float4 o4 = {s0, s1, s2, s3};
            *(float4*)(out + (size_t)(b0 + bl) * 128 + og * 4) = o4;
        }
    }
}

// ---------- generic two-kernel fallback (any O/H/B) ----------
__global__ void compute_T_kernel(const float* __restrict__ W_in,
                                 const float* __restrict__ W_out,
                                 int H, float alpha)
{
    const int o = blockIdx.x;
    const int tid = threadIdx.x;
    CLIFFORD_CIJ();
    float acc[8];
    #pragma unroll
    for (int i = 0; i < 8; i++) acc[i] = 0.0f;
    const float* woutBase = W_out + (size_t)o * H * 8;
    for (int h = tid; h < H; h += blockDim.x) {
        float4 a0 = *(const float4*)(W_in + h * 8);
        float4 a1 = *(const float4*)(W_in + h * 8 + 4);
        float4 b0 = *(const float4*)(woutBase + h * 8);
        float4 b1 = *(const float4*)(woutBase + h * 8 + 4);
        float win[8]  = {a0.x, a0.y, a0.z, a0.w, a1.x, a1.y, a1.z, a1.w};
        float wout[8] = {b0.x, b0.y, b0.z, b0.w, b1.x, b1.y, b1.z, b1.w};
        #pragma unroll
        for (int i = 0; i < 8; i++) {
            float s = 0.0f;
            #pragma unroll
            for (int j = 0; j < 8; j++)
                s += cij[i][j] * win[j] * wout[i ^ j];
            acc[i] += s;
        }
    }
    #pragma unroll
    for (int i = 0; i < 8; i++)
        #pragma unroll
        for (int off = 16; off > 0; off >>= 1)
            acc[i] += __shfl_xor_sync(0xffffffff, acc[i], off);
    __shared__ float red[8][8];
    const int lane = tid & 31, w = tid >> 5;
    const int nw = blockDim.x >> 5;
    if (lane == 0) {
        #pragma unroll
        for (int i = 0; i < 8; i++) red[w][i] = acc[i];
    }
    __syncthreads();
    if (tid < 8) {
        float s = 0.0f;
        for (int ww = 0; ww < nw; ww++) s += red[ww][tid];
        g_T[o * 8 + tid] = alpha * s;
    }
}

__global__ void finalize_generic_kernel(const float* __restrict__ x,
                                        float* __restrict__ out, int O)
{
    extern __shared__ float Tg[];  // [8][O] transposed
    for (int idx = threadIdx.x; idx < O * 8; idx += blockDim.x) {
        int o = idx >> 3, i = idx & 7;
        Tg[i * O + o] = g_T[idx];
    }
    __syncthreads();
    const int b = blockIdx.x;
    float4 x0 = *(const float4*)(x + b * 8);
    float4 x1 = *(const float4*)(x + b * 8 + 4);
    for (int o = threadIdx.x; o < O; o += blockDim.x) {
        float s = x0.x * Tg[o]         + x0.y * Tg[O + o]
                + x0.z * Tg[2 * O + o] + x0.w * Tg[3 * O + o]
                + x1.x * Tg[4 * O + o] + x1.y * Tg[5 * O + o]
                + x1.z * Tg[6 * O + o] + x1.w * Tg[7 * O + o];
        out[(size_t)b * O + o] = s;
    }
}

extern "C" void kernel_launch(void* const* d_in, const int* in_sizes, int n_in,
                              void* d_out, int out_size)
{
    const float* x     = (const float*)d_in[0];  // [B,8]
    const float* W_in  = (const float*)d_in[1];  // [H,1,8]
    const float* W_out = (const float*)d_in[2];  // [O,H,8]

    const int B = in_sizes[0] / 8;
    const int H = in_sizes[1] / 8;
    const int O = in_sizes[2] / (H * 8);

    // alpha = 1 - (1-dt)^n_free, dt=0.1, n_free=10
    double p = 1.0;
    for (int i = 0; i < 10; i++) p *= 0.9;
    const float alpha = (float)(1.0 - p);

    const int nF = B / F_ROWS;   // consumer blocks
    // Residency bound: 256-thread blocks, <=8/SM, 152 SMs -> 1216 resident.
    if (O == 128 && (B % F_ROWS) == 0 && (O + nF) <= 1024) {
        void* done_ptr = nullptr;
        cudaGetSymbolAddress(&done_ptr, g_done);
        cudaMemsetAsync(done_ptr, 0, sizeof(unsigned), 0);
        fused_kernel<<<O + nF, 256>>>(x, W_in, W_out, (float*)d_out, H, O, alpha);
    } else {
        compute_T_kernel<<<O, 256>>>(W_in, W_out, H, alpha);
        finalize_generic_kernel<<<B, 128, O * 8 * sizeof(float)>>>(x, (float*)d_out, O);
    }
}

// round 6
// speedup vs baseline: 1.2610x; 1.1875x over previous
#include <cuda_runtime.h>

// Precontracted weight matrix T[o][i], alpha folded in (O<=1024).
__device__ float g_T[8192];

// Sign of e_a * e_b reordering for Cl(3,0) (all metric signs +1).
__device__ __forceinline__ float blade_sign(int a, int b) {
    int swaps = 0;
    int t = a >> 1;
    while (t) { swaps += __popc(t & b); t >>= 1; }
    return (swaps & 1) ? -1.0f : 1.0f;
}

#define CLIFFORD_CIJ()                                             \
    float sigma[8];                                                \
    _Pragma("unroll")                                              \
    for (int k = 0; k < 8; k++) sigma[k] = blade_sign(k, k);       \
    float cij[8][8];                                               \
    _Pragma("unroll")                                              \
    for (int i = 0; i < 8; i++)                                    \
        _Pragma("unroll")                                          \
        for (int j = 0; j < 8; j++)                                \
            cij[i][j] = blade_sign(i, j) * sigma[i ^ j];

// T[o,i] = alpha * sum_{h,j} W_in[h,j]*S[i,j]*sigma[i^j]*W_out[o,h,i^j]
// One block per o, 512 threads: for H=512 each thread handles exactly one h,
// so all global loads issue up front (max MLP, no loop-carried chain).
__global__ __launch_bounds__(512)
void compute_T_kernel(const float* __restrict__ W_in,
                      const float* __restrict__ W_out,
                      int H, float alpha)
{
    const int o = blockIdx.x;
    const int tid = threadIdx.x;

    CLIFFORD_CIJ();

    float acc[8];
    #pragma unroll
    for (int i = 0; i < 8; i++) acc[i] = 0.0f;

    const float* woutBase = W_out + (size_t)o * H * 8;
    for (int h = tid; h < H; h += 512) {
        float4 a0 = *(const float4*)(W_in + h * 8);
        float4 a1 = *(const float4*)(W_in + h * 8 + 4);
        float4 b0 = *(const float4*)(woutBase + h * 8);
        float4 b1 = *(const float4*)(woutBase + h * 8 + 4);
        float win[8]  = {a0.x, a0.y, a0.z, a0.w, a1.x, a1.y, a1.z, a1.w};
        float wout[8] = {b0.x, b0.y, b0.z, b0.w, b1.x, b1.y, b1.z, b1.w};
        #pragma unroll
        for (int i = 0; i < 8; i++) {
            float s = 0.0f;
            #pragma unroll
            for (int j = 0; j < 8; j++)
                s += cij[i][j] * win[j] * wout[i ^ j];
            acc[i] += s;
        }
    }

    #pragma unroll
    for (int i = 0; i < 8; i++)
        #pragma unroll
        for (int off = 16; off > 0; off >>= 1)
            acc[i] += __shfl_xor_sync(0xffffffff, acc[i], off);

    __shared__ float red[16][8];
    const int lane = tid & 31, w = tid >> 5;
    if (lane == 0) {
        #pragma unroll
        for (int i = 0; i < 8; i++) red[w][i] = acc[i];
    }
    __syncthreads();
    if (tid < 8) {
        float s = 0.0f;
        #pragma unroll
        for (int ww = 0; ww < 16; ww++) s += red[ww][tid];
        g_T[o * 8 + tid] = alpha * s;
    }
}

// Finalize (O==128): 32 rows/block, 128 blocks (single wave).
// Thread (bq, og): bq = tid>>5 picks row slice, og = tid&31 picks 4 outputs.
#define F_ROWS 32
__global__ __launch_bounds__(256)
void finalize128_kernel(const float* __restrict__ x,
                        float* __restrict__ out)
{
    __shared__ float Ts[32 * 33];      // 32 o-groups x 32 floats, stride 33
    __shared__ float xs[F_ROWS * 9];   // 32 rows x 8 (+pad)

    const int tid = threadIdx.x;
    const int b0 = blockIdx.x * F_ROWS;

    // Stage T: one float4 LDG + 4 conflict-free scalar STS per thread.
    {
        float4 g = *((const float4*)g_T + tid);   // 1024 floats total
        const float v[4] = {g.x, g.y, g.z, g.w};
        #pragma unroll
        for (int e = 0; e < 4; e++) {
            int idx = tid * 4 + e;                 // = o*8 + i
            Ts[(idx >> 5) * 33 + (idx & 31)] = v[e];
        }
    }
    // Stage x: 32 rows * 8 = 256 floats = 64 float4.
    if (tid < F_ROWS * 2) {
        float4 g = *((const float4*)(x + (size_t)b0 * 8) + tid);
        const float v[4] = {g.x, g.y, g.z, g.w};
        #pragma unroll
        for (int e = 0; e < 4; e++) {
            int idx = tid * 4 + e;                 // row = idx>>3, col = idx&7
            xs[(idx >> 3) * 9 + (idx & 7)] = v[e];
        }
    }
    __syncthreads();

    const int og = tid & 31;
    const int bq = tid >> 5;   // 0..7

    float t[32];
    #pragma unroll
    for (int k = 0; k < 32; k++) t[k] = Ts[og * 33 + k];   // conflict-free

    #pragma unroll
    for (int r = 0; r < F_ROWS / 8; r++) {
        const int bl = bq + r * 8;
        float xv[8];
        #pragma unroll
        for (int i = 0; i < 8; i++) xv[i] = xs[bl * 9 + i]; // warp broadcast

        float s0 = 0, s1 = 0, s2 = 0, s3 = 0;
        #pragma unroll
        for (int i = 0; i < 8; i++) {
            s0 += xv[i] * t[i];
            s1 += xv[i] * t[8 + i];
            s2 += xv[i] * t[16 + i];
            s3 += xv[i] * t[24 + i];
        }
        float4 o4 = {s0, s1, s2, s3};
        *(float4*)(out + (size_t)(b0 + bl) * 128 + og * 4) = o4;
    }
}

// ---------- generic fallbacks (any O/H/B) ----------
__global__ void compute_T_generic(const float* __restrict__ W_in,
                                  const float* __restrict__ W_out,
                                  int H, float alpha)
{
    const int o = blockIdx.x;
    const int tid = threadIdx.x;
    CLIFFORD_CIJ();
    float acc[8];
    #pragma unroll
    for (int i = 0; i < 8; i++) acc[i] = 0.0f;
    const float* woutBase = W_out + (size_t)o * H * 8;
    for (int h = tid; h < H; h += blockDim.x) {
        float4 a0 = *(const float4*)(W_in + h * 8);
        float4 a1 = *(const float4*)(W_in + h * 8 + 4);
        float4 b0 = *(const float4*)(woutBase + h * 8);
        float4 b1 = *(const float4*)(woutBase + h * 8 + 4);
        float win[8]  = {a0.x, a0.y, a0.z, a0.w, a1.x, a1.y, a1.z, a1.w};
        float wout[8] = {b0.x, b0.y, b0.z, b0.w, b1.x, b1.y, b1.z, b1.w};
        #pragma unroll
        for (int i = 0; i < 8; i++) {
            float s = 0.0f;
            #pragma unroll
            for (int j = 0; j < 8; j++)
                s += cij[i][j] * win[j] * wout[i ^ j];
            acc[i] += s;
        }
    }
    #pragma unroll
    for (int i = 0; i < 8; i++)
        #pragma unroll
        for (int off = 16; off > 0; off >>= 1)
            acc[i] += __shfl_xor_sync(0xffffffff, acc[i], off);
    __shared__ float red[8][8];
    const int lane = tid & 31, w = tid >> 5;
    const int nw = blockDim.x >> 5;
    if (lane == 0) {
        #pragma unroll
        for (int i = 0; i < 8; i++) red[w][i] = acc[i];
    }
    __syncthreads();
    if (tid < 8) {
        float s = 0.0f;
        for (int ww = 0; ww < nw; ww++) s += red[ww][tid];
        g_T[o * 8 + tid] = alpha * s;
    }
}

__global__ void finalize_generic_kernel(const float* __restrict__ x,
                                        float* __restrict__ out, int O)
{
    extern __shared__ float Tg[];  // [8][O] transposed
    for (int idx = threadIdx.x; idx < O * 8; idx += blockDim.x) {
        int o = idx >> 3, i = idx & 7;
        Tg[i * O + o] = g_T[idx];
    }
    __syncthreads();
    const int b = blockIdx.x;
    float4 x0 = *(const float4*)(x + b * 8);
    float4 x1 = *(const float4*)(x + b * 8 + 4);
    for (int o = threadIdx.x; o < O; o += blockDim.x) {
        float s = x0.x * Tg[o]         + x0.y * Tg[O + o]
                + x0.z * Tg[2 * O + o] + x0.w * Tg[3 * O + o]
                + x1.x * Tg[4 * O + o] + x1.y * Tg[5 * O + o]
                + x1.z * Tg[6 * O + o] + x1.w * Tg[7 * O + o];
        out[(size_t)b * O + o] = s;
    }
}

extern "C" void kernel_launch(void* const* d_in, const int* in_sizes, int n_in,
                              void* d_out, int out_size)
{
    const float* x     = (const float*)d_in[0];  // [B,8]
    const float* W_in  = (const float*)d_in[1];  // [H,1,8]
    const float* W_out = (const float*)d_in[2];  // [O,H,8]

    const int B = in_sizes[0] / 8;
    const int H = in_sizes[1] / 8;
    const int O = in_sizes[2] / (H * 8);

    // alpha = 1 - (1-dt)^n_free, dt=0.1, n_free=10
    double p = 1.0;
    for (int i = 0; i < 10; i++) p *= 0.9;
    const float alpha = (float)(1.0 - p);

    if (O == 128 && (B % F_ROWS) == 0) {
        compute_T_kernel<<<O, 512>>>(W_in, W_out, H, alpha);
        finalize128_kernel<<<B / F_ROWS, 256>>>(x, (float*)d_out);
    } else {
        compute_T_generic<<<O, 256>>>(W_in, W_out, H, alpha);
        finalize_generic_kernel<<<B, 128, O * 8 * sizeof(float)>>>(x, (float*)d_out, O);
    }
}

// round 7
// speedup vs baseline: 1.2657x; 1.0037x over previous
#include <cuda_runtime.h>

// Precontracted weight matrix T[o][i], alpha folded in (O<=1024).
__device__ float g_T[8192];
// Handshake counters: zero at module load; kernel restores them to zero
// before exiting, so every graph replay sees the same initial state.
__device__ unsigned g_done = 0;
__device__ unsigned g_exit = 0;

// Sign of e_a * e_b reordering for Cl(3,0) (all metric signs +1).
__device__ __forceinline__ float blade_sign(int a, int b) {
    int swaps = 0;
    int t = a >> 1;
    while (t) { swaps += __popc(t & b); t >>= 1; }
    return (swaps & 1) ? -1.0f : 1.0f;
}

#define CLIFFORD_CIJ()                                             \
    float sigma[8];                                                \
    _Pragma("unroll")                                              \
    for (int k = 0; k < 8; k++) sigma[k] = blade_sign(k, k);       \
    float cij[8][8];                                               \
    _Pragma("unroll")                                              \
    for (int i = 0; i < 8; i++)                                    \
        _Pragma("unroll")                                          \
        for (int j = 0; j < 8; j++)                                \
            cij[i][j] = blade_sign(i, j) * sigma[i ^ j];

// Fused single-launch kernel for O==128, B%128==0.
// Grid = 128 blocks x 512 threads; all blocks co-resident (<=152 SMs).
// Block bid: (1) produces T[bid,:], (2) consumes 32 batch rows.
#define FUSED_BLOCKS 128
__global__ __launch_bounds__(512)
void fused_kernel(const float* __restrict__ x,
                  const float* __restrict__ W_in,
                  const float* __restrict__ W_out,
                  float* __restrict__ out,
                  int H, int rowsPerBlock, float alpha)
{
    __shared__ float Ts[32 * 33];        // 32 o-groups x 32 floats, stride 33
    __shared__ float xs[32 * 9];         // up to 32 rows x 8 (+pad)
    __shared__ float red[16][8];

    const int tid = threadIdx.x;
    const int o = blockIdx.x;
    const int b0 = blockIdx.x * rowsPerBlock;

    // ---- stage x early (independent of producer chain) ----
    const int nxvec = rowsPerBlock * 2;  // float4s
    if (tid < nxvec) {
        float4 g = *((const float4*)(x + (size_t)b0 * 8) + tid);
        const float v[4] = {g.x, g.y, g.z, g.w};
        #pragma unroll
        for (int e = 0; e < 4; e++) {
            int idx = tid * 4 + e;       // row = idx>>3, col = idx&7
            xs[(idx >> 3) * 9 + (idx & 7)] = v[e];
        }
    }

    // ---- produce T[o,:] ----
    {
        CLIFFORD_CIJ();
        float acc[8];
        #pragma unroll
        for (int i = 0; i < 8; i++) acc[i] = 0.0f;

        const float* woutBase = W_out + (size_t)o * H * 8;
        for (int h = tid; h < H; h += 512) {
            float4 a0 = *(const float4*)(W_in + h * 8);
            float4 a1 = *(const float4*)(W_in + h * 8 + 4);
            float4 b0v = *(const float4*)(woutBase + h * 8);
            float4 b1v = *(const float4*)(woutBase + h * 8 + 4);
            float win[8]  = {a0.x, a0.y, a0.z, a0.w, a1.x, a1.y, a1.z, a1.w};
            float wout[8] = {b0v.x, b0v.y, b0v.z, b0v.w, b1v.x, b1v.y, b1v.z, b1v.w};
            #pragma unroll
            for (int i = 0; i < 8; i++) {
                float s = 0.0f;
                #pragma unroll
                for (int j = 0; j < 8; j++)
                    s += cij[i][j] * win[j] * wout[i ^ j];
                acc[i] += s;
            }
        }
        #pragma unroll
        for (int i = 0; i < 8; i++)
            #pragma unroll
            for (int off = 16; off > 0; off >>= 1)
                acc[i] += __shfl_xor_sync(0xffffffff, acc[i], off);

        const int lane = tid & 31, w = tid >> 5;
        if (lane == 0) {
            #pragma unroll
            for (int i = 0; i < 8; i++) red[w][i] = acc[i];
        }
        __syncthreads();
        if (tid < 8) {
            float s = 0.0f;
            #pragma unroll
            for (int ww = 0; ww < 16; ww++) s += red[ww][tid];
            g_T[o * 8 + tid] = alpha * s;
        }
        __threadfence();   // release g_T stores
        __syncthreads();
        if (tid == 0) atomicAdd(&g_done, 1u);
    }

    // ---- wait for all producers ----
    if (tid == 0) {
        while (*(volatile unsigned*)&g_done < (unsigned)FUSED_BLOCKS) { }
    }
    __syncthreads();
    __threadfence();       // acquire: order g_T loads after flag observation

    // ---- stage T into shared (vectorized, conflict-free) ----
    if (tid < 256) {
        float4 g = *((const float4*)g_T + tid);   // 1024 floats
        const float v[4] = {g.x, g.y, g.z, g.w};
        #pragma unroll
        for (int e = 0; e < 4; e++) {
            int idx = tid * 4 + e;
            Ts[(idx >> 5) * 33 + (idx & 31)] = v[e];
        }
    }
    __syncthreads();

    // ---- consume: rowsPerBlock rows, 512 threads ----
    const int og = tid & 31;
    const int bq = tid >> 5;   // 0..15

    float t[32];
    #pragma unroll
    for (int k = 0; k < 32; k++) t[k] = Ts[og * 33 + k];   // conflict-free

    for (int bl = bq; bl < rowsPerBlock; bl += 16) {
        float xv[8];
        #pragma unroll
        for (int i = 0; i < 8; i++) xv[i] = xs[bl * 9 + i];  // warp broadcast

        float s0 = 0, s1 = 0, s2 = 0, s3 = 0;
        #pragma unroll
        for (int i = 0; i < 8; i++) {
            s0 += xv[i] * t[i];
            s1 += xv[i] * t[8 + i];
            s2 += xv[i] * t[16 + i];
            s3 += xv[i] * t[24 + i];
        }
        float4 o4 = {s0, s1, s2, s3};
        *(float4*)(out + (size_t)(b0 + bl) * 128 + og * 4) = o4;
    }

    // ---- reset handshake for the next replay (last block out) ----
    __syncthreads();
    if (tid == 0) {
        unsigned prev = atomicAdd(&g_exit, 1u);
        if (prev == FUSED_BLOCKS - 1) {
            g_done = 0;
            g_exit = 0;
            __threadfence();
        }
    }
}

// ---------- generic two-kernel fallback (any O/H/B) ----------
__global__ void compute_T_generic(const float* __restrict__ W_in,
                                  const float* __restrict__ W_out,
                                  int H, float alpha)
{
    const int o = blockIdx.x;
    const int tid = threadIdx.x;
    CLIFFORD_CIJ();
    float acc[8];
    #pragma unroll
    for (int i = 0; i < 8; i++) acc[i] = 0.0f;
    const float* woutBase = W_out + (size_t)o * H * 8;
    for (int h = tid; h < H; h += blockDim.x) {
        float4 a0 = *(const float4*)(W_in + h * 8);
        float4 a1 = *(const float4*)(W_in + h * 8 + 4);
        float4 b0 = *(const float4*)(woutBase + h * 8);
        float4 b1 = *(const float4*)(woutBase + h * 8 + 4);
        float win[8]  = {a0.x, a0.y, a0.z, a0.w, a1.x, a1.y, a1.z, a1.w};
        float wout[8] = {b0.x, b0.y, b0.z, b0.w, b1.x, b1.y, b1.z, b1.w};
        #pragma unroll
        for (int i = 0; i < 8; i++) {
            float s = 0.0f;
            #pragma unroll
            for (int j = 0; j < 8; j++)
                s += cij[i][j] * win[j] * wout[i ^ j];
            acc[i] += s;
        }
    }
    #pragma unroll
    for (int i = 0; i < 8; i++)
        #pragma unroll
        for (int off = 16; off > 0; off >>= 1)
            acc[i] += __shfl_xor_sync(0xffffffff, acc[i], off);
    __shared__ float red[8][8];
    const int lane = tid & 31, w = tid >> 5;
    const int nw = blockDim.x >> 5;
    if (lane == 0) {
        #pragma unroll
        for (int i = 0; i < 8; i++) red[w][i] = acc[i];
    }
    __syncthreads();
    if (tid < 8) {
        float s = 0.0f;
        for (int ww = 0; ww < nw; ww++) s += red[ww][tid];
        g_T[o * 8 + tid] = alpha * s;
    }
}

__global__ void finalize_generic_kernel(const float* __restrict__ x,
                                        float* __restrict__ out, int O)
{
    extern __shared__ float Tg[];  // [8][O] transposed
    for (int idx = threadIdx.x; idx < O * 8; idx += blockDim.x) {
        int o = idx >> 3, i = idx & 7;
        Tg[i * O + o] = g_T[idx];
    }
    __syncthreads();
    const int b = blockIdx.x;
    float4 x0 = *(const float4*)(x + b * 8);
    float4 x1 = *(const float4*)(x + b * 8 + 4);
    for (int o = threadIdx.x; o < O; o += blockDim.x) {
        float s = x0.x * Tg[o]         + x0.y * Tg[O + o]
                + x0.z * Tg[2 * O + o] + x0.w * Tg[3 * O + o]
                + x1.x * Tg[4 * O + o] + x1.y * Tg[5 * O + o]
                + x1.z * Tg[6 * O + o] + x1.w * Tg[7 * O + o];
        out[(size_t)b * O + o] = s;
    }
}

extern "C" void kernel_launch(void* const* d_in, const int* in_sizes, int n_in,
                              void* d_out, int out_size)
{
    const float* x     = (const float*)d_in[0];  // [B,8]
    const float* W_in  = (const float*)d_in[1];  // [H,1,8]
    const float* W_out = (const float*)d_in[2];  // [O,H,8]

    const int B = in_sizes[0] / 8;
    const int H = in_sizes[1] / 8;
    const int O = in_sizes[2] / (H * 8);

    // alpha = 1 - (1-dt)^n_free, dt=0.1, n_free=10
    double p = 1.0;
    for (int i = 0; i < 10; i++) p *= 0.9;
    const float alpha = (float)(1.0 - p);

    const int rowsPerBlock = B / FUSED_BLOCKS;
    if (O == FUSED_BLOCKS && (B % FUSED_BLOCKS) == 0 &&
        rowsPerBlock >= 16 && rowsPerBlock <= 32 && (rowsPerBlock % 16) == 0) {
        fused_kernel<<<FUSED_BLOCKS, 512>>>(x, W_in, W_out, (float*)d_out,
                                            H, rowsPerBlock, alpha);
    } else {
        compute_T_generic<<<O, 256>>>(W_in, W_out, H, alpha);
        finalize_generic_kernel<<<B, 128, O * 8 * sizeof(float)>>>(x, (float*)d_out, O);
    }
}